// round 11
// baseline (speedup 1.0000x reference)
#include <cuda_runtime.h>
#include <cuda_bf16.h>

// Problem dims
#define Bn   8
#define Nn   6
#define Dn   41
#define FHn  8
#define FWn  22
#define Cn   64
#define NX0  200
#define NX1  200

constexpr int NPRIME      = Bn * Nn * Dn * FHn * FWn;     // 346368 (=1353*256)
constexpr int PTS_PER_B   = Nn * Dn * FHn * FWn;          // 43296
constexpr int PTS_PER_N   = Dn * FHn * FWn;               // 7216
constexpr int PTS_PER_D   = FHn * FWn;                    // 176
constexpr int VOX_PER_B   = NX0 * NX1;                    // 40000
constexpr int GRID_FLOATS = Bn * VOX_PER_B * Cn;          // 20,480,000
constexpr int TILES_PER_B = VOX_PER_B / 64;               // 625
constexpr int NTILES      = Bn * TILES_PER_B;             // 5000

// State protocol (consume-before-produce, stream-ordered):
//   module load: g_scratch = 0, g_touched = 0            (CUDA zero-init)
//   K0 (call start): for each tile with g_touched==1 -> zero its scratch,
//                    then clear the flag. After K0: scratch all-zero, flags 0.
//   K1: sets flags (before/with its atomics), accumulates into scratch.
//   K2: reads flags + scratch, writes out. Leaves both dirty for next K0.
// Every atomic to tile T is preceded (program order, same kernel) by a store
// of g_touched[T]=1, so K0 can never under-zero.
__device__ __align__(16) float g_scratch[GRID_FLOATS];
__device__ unsigned int g_touched[NTILES];

// ---------------------------------------------------------------------------
__device__ __forceinline__ void inv3(const float* m, float* o) {
    float a = m[0], b = m[1], c = m[2];
    float d = m[3], e = m[4], f = m[5];
    float g = m[6], h = m[7], i = m[8];
    float A  = e * i - f * h;
    float Bc = -(d * i - f * g);
    float Cc = d * h - e * g;
    float det = a * A + b * Bc + c * Cc;
    float inv = 1.0f / det;
    o[0] = A * inv;            o[1] = (c * h - b * i) * inv; o[2] = (b * f - c * e) * inv;
    o[3] = Bc * inv;           o[4] = (a * i - c * g) * inv; o[5] = (c * d - a * f) * inv;
    o[6] = Cc * inv;           o[7] = (b * g - a * h) * inv; o[8] = (a * e - b * d) * inv;
}

// K0: consume previous call's touched set -> zero those scratch tiles,
// clear flags. One block per tile.
__global__ void clean_kernel() {
    int blk = blockIdx.x;                  // NTILES
    if (g_touched[blk] == 0) return;
    float4* dst = reinterpret_cast<float4*>(g_scratch) + (size_t)blk * 1024;
    int t = threadIdx.x;                   // 256
    float4 z = make_float4(0.f, 0.f, 0.f, 0.f);
    #pragma unroll
    for (int k = 0; k < 4; k++) dst[t + 256 * k] = z;
    if (t == 0) g_touched[blk] = 0;
}

// ---------------------------------------------------------------------------
// K1: camera matrices per block in smem; geometry once per point; kept
// points stream their 256B feature row and scatter it with float4 REDs.
__global__ void geom_scatter_kernel(const float4* __restrict__ feats,
                                    const float* __restrict__ rots,
                                    const float* __restrict__ trans,
                                    const float* __restrict__ intrins,
                                    const float* __restrict__ post_rots,
                                    const float* __restrict__ post_trans) {
    __shared__ float sM[48 * 24];
    int t = threadIdx.x;

    if (t < Bn * Nn) {
        int cam = t;
        float M1[9], Ki[9], M2[9];
        inv3(post_rots + cam * 9, M1);
        inv3(intrins + cam * 9, Ki);
        const float* R = rots + cam * 9;
        #pragma unroll
        for (int r = 0; r < 3; r++)
            #pragma unroll
            for (int c = 0; c < 3; c++)
                M2[r * 3 + c] = R[r * 3 + 0] * Ki[0 + c] + R[r * 3 + 1] * Ki[3 + c] + R[r * 3 + 2] * Ki[6 + c];
        const float* pt = post_trans + cam * 3;
        float t1[3];
        #pragma unroll
        for (int r = 0; r < 3; r++)
            t1[r] = M1[r * 3 + 0] * pt[0] + M1[r * 3 + 1] * pt[1] + M1[r * 3 + 2] * pt[2];

        float* o = sM + cam * 24;
        #pragma unroll
        for (int k = 0; k < 9; k++) o[k] = M1[k];
        #pragma unroll
        for (int k = 0; k < 3; k++) o[9 + k] = t1[k];
        #pragma unroll
        for (int k = 0; k < 9; k++) o[12 + k] = M2[k];
        const float* tr = trans + cam * 3;
        #pragma unroll
        for (int k = 0; k < 3; k++) o[21 + k] = tr[k];
    }
    __syncthreads();

    int p = blockIdx.x * blockDim.x + t;   // NPRIME divisible by 256

    int b  = p / PTS_PER_B;
    int r  = p - b * PTS_PER_B;
    int n  = r / PTS_PER_N;
    int r2 = r - n * PTS_PER_N;
    int d  = r2 / PTS_PER_D;
    int r3 = r2 - d * PTS_PER_D;
    int h  = r3 / FWn;
    int w  = r3 - h * FWn;

    const float* M = sM + (b * Nn + n) * 24;

    float fx = (float)w * (351.0f / 21.0f);
    float fy = (float)h * (127.0f / 7.0f);
    float fd = 4.0f + (float)d;

    // pt = inv(post_rots) @ (f - post_trans)  ==  M1 @ f - t1
    float px = M[0] * fx + M[1] * fy + M[2] * fd - M[9];
    float py = M[3] * fx + M[4] * fy + M[5] * fd - M[10];
    float pz = M[6] * fx + M[7] * fy + M[8] * fd - M[11];

    // unproject + rotate to ego frame
    float x2 = px * pz;
    float y2 = py * pz;
    float z2 = pz;
    float gxw = M[12] * x2 + M[13] * y2 + M[14] * z2 + M[21];
    float gyw = M[15] * x2 + M[16] * y2 + M[17] * z2 + M[22];
    float gzw = M[18] * x2 + M[19] * y2 + M[20] * z2 + M[23];

    // voxelize (truncate toward zero matches astype(int32))
    int gx = (int)((gxw + 50.0f) / 0.5f);
    int gy = (int)((gyw + 50.0f) / 0.5f);
    int gz = (int)((gzw + 10.0f) / 20.0f);

    if (gx < 0 || gx >= NX0 || gy < 0 || gy >= NX1 || gz != 0) return;

    int voxInB = gx * NX1 + gy;
    int vox    = b * VOX_PER_B + voxInB;
    g_touched[vox >> 6] = 1;               // flag BEFORE atomics (program order)

    const float4* src = feats + (size_t)p * 16;              // this point's 256B row
    float4* dst = reinterpret_cast<float4*>(g_scratch) + (size_t)vox * 16;

    // two rounds of 8: MLP=8 loads, then fire-and-forget REDs
    float4 v[8];
    #pragma unroll
    for (int k = 0; k < 8; k++) v[k] = __ldcs(&src[k]);
    #pragma unroll
    for (int k = 0; k < 8; k++) atomicAdd(&dst[k], v[k]);
    #pragma unroll
    for (int k = 0; k < 8; k++) v[k] = __ldcs(&src[8 + k]);
    #pragma unroll
    for (int k = 0; k < 8; k++) atomicAdd(&dst[8 + k], v[k]);
}

// ---------------------------------------------------------------------------
// K2: finalize. Untouched -> zeros to out; touched -> transpose scratch tile.
// Leaves scratch/flags dirty; next call's K0 consumes them.
__global__ void finalize_kernel(float* __restrict__ out) {
    __shared__ float tile[64][65];
    int blk  = blockIdx.x;                 // NTILES
    int b    = blk / TILES_PER_B;
    int tIdx = blk - b * TILES_PER_B;
    int pos0 = tIdx * 64;
    int t    = threadIdx.x;                // 256

    float* dst = out + (size_t)b * Cn * VOX_PER_B + pos0;

    if (g_touched[blk] == 0) {
        float4 z = make_float4(0.f, 0.f, 0.f, 0.f);
        #pragma unroll
        for (int k = 0; k < 4; k++) {
            int i = t + 256 * k;           // 0..1023 float4 slots
            int c = i >> 4;
            int p = (i & 15) * 4;
            __stcs(reinterpret_cast<float4*>(dst + (size_t)c * VOX_PER_B + p), z);
        }
        return;
    }

    const float4* src4 = reinterpret_cast<const float4*>(g_scratch) + (size_t)blk * 1024;
    #pragma unroll
    for (int k = 0; k < 4; k++) {
        int i = t + 256 * k;
        float4 v = __ldcs(&src4[i]);       // single-use: evict-first
        int pos = i >> 4;
        int c4  = (i & 15) * 4;
        tile[pos][c4 + 0] = v.x;
        tile[pos][c4 + 1] = v.y;
        tile[pos][c4 + 2] = v.z;
        tile[pos][c4 + 3] = v.w;
    }
    __syncthreads();

    #pragma unroll
    for (int k = 0; k < 4; k++) {
        int i = t + 256 * k;
        int c = i >> 4;
        int p = (i & 15) * 4;
        float4 v = make_float4(tile[p + 0][c], tile[p + 1][c],
                               tile[p + 2][c], tile[p + 3][c]);
        __stcs(reinterpret_cast<float4*>(dst + (size_t)c * VOX_PER_B + p), v);
    }
}

// ---------------------------------------------------------------------------
extern "C" void kernel_launch(void* const* d_in, const int* in_sizes, int n_in,
                              void* d_out, int out_size) {
    const float* x_feats    = (const float*)d_in[0];
    const float* rots       = (const float*)d_in[1];
    const float* trans      = (const float*)d_in[2];
    const float* intrins    = (const float*)d_in[3];
    const float* post_rots  = (const float*)d_in[4];
    const float* post_trans = (const float*)d_in[5];
    float* out = (float*)d_out;

    // K0: zero scratch tiles dirtied by the previous call; clear flags.
    clean_kernel<<<NTILES, 256>>>();
    // K1: geometry + direct feature scatter (flags set before atomics).
    geom_scatter_kernel<<<NPRIME / 256, 256>>>(
        reinterpret_cast<const float4*>(x_feats),
        rots, trans, intrins, post_rots, post_trans);
    // K2: transpose touched tiles / zero untouched into [B, C, 200, 200].
    finalize_kernel<<<NTILES, 256>>>(out);
}

// round 12
// speedup vs baseline: 1.2442x; 1.2442x over previous
#include <cuda_runtime.h>
#include <cuda_bf16.h>

// Problem dims
#define Bn   8
#define Nn   6
#define Dn   41
#define FHn  8
#define FWn  22
#define Cn   64
#define NX0  200
#define NX1  200

constexpr int NPRIME      = Bn * Nn * Dn * FHn * FWn;     // 346368 (=1353*256)
constexpr int PTS_PER_B   = Nn * Dn * FHn * FWn;          // 43296
constexpr int PTS_PER_N   = Dn * FHn * FWn;               // 7216
constexpr int PTS_PER_D   = FHn * FWn;                    // 176
constexpr int VOX_PER_B   = NX0 * NX1;                    // 40000
constexpr int GRID_FLOATS = Bn * VOX_PER_B * Cn;          // 20,480,000
constexpr int TILES_PER_B = VOX_PER_B / 64;               // 625
constexpr int NTILES      = Bn * TILES_PER_B;             // 5000

// Protocol (validated in R11): module load zero-inits everything. K0 consumes
// the PREVIOUS call's touched flags (zero those scratch tiles, clear flags);
// K1 sets flags before its atomics and accumulates; K2 reads flags+scratch and
// writes out, leaving both dirty for the next call's K0. Stream order makes
// each call self-consistent.
__device__ __align__(16) float g_scratch[GRID_FLOATS];
__device__ __align__(16) unsigned int g_touched[NTILES];

// ---------------------------------------------------------------------------
__device__ __forceinline__ void inv3(const float* m, float* o) {
    float a = m[0], b = m[1], c = m[2];
    float d = m[3], e = m[4], f = m[5];
    float g = m[6], h = m[7], i = m[8];
    float A  = e * i - f * h;
    float Bc = -(d * i - f * g);
    float Cc = d * h - e * g;
    float det = a * A + b * Bc + c * Cc;
    float inv = 1.0f / det;
    o[0] = A * inv;            o[1] = (c * h - b * i) * inv; o[2] = (b * f - c * e) * inv;
    o[3] = Bc * inv;           o[4] = (a * i - c * g) * inv; o[5] = (c * d - a * f) * inv;
    o[6] = Cc * inv;           o[7] = (b * g - a * h) * inv; o[8] = (a * e - b * d) * inv;
}

// K0: zero scratch tiles dirtied by the previous call; clear flags.
// 4 tiles per block (uint4 flag load) to cut flag-check overhead.
__global__ void clean_kernel() {
    int base = blockIdx.x * 4;             // 1250 blocks
    int t = threadIdx.x;                   // 256
    uint4 f = *reinterpret_cast<const uint4*>(&g_touched[base]);
    float4 z = make_float4(0.f, 0.f, 0.f, 0.f);
    unsigned fl[4] = {f.x, f.y, f.z, f.w};
    #pragma unroll
    for (int k = 0; k < 4; k++) {
        if (fl[k]) {
            float4* dst = reinterpret_cast<float4*>(g_scratch) + (size_t)(base + k) * 1024;
            #pragma unroll
            for (int j = 0; j < 4; j++) dst[t + 256 * j] = z;
        }
    }
    if (t < 4 && fl[t]) g_touched[base + t] = 0;
}

// ---------------------------------------------------------------------------
// K1: camera matrices per block in smem; geometry once per point; then the
// warp cooperatively scatters its kept points 2-at-a-time (lanes 0-15 serve
// the first, 16-31 the second) -> identical coalescing to the R8 scatter
// (one 512B fully-used line set per LDG.128) with no list and no extra launch.
__global__ void geom_scatter_kernel(const float4* __restrict__ feats,
                                    const float* __restrict__ rots,
                                    const float* __restrict__ trans,
                                    const float* __restrict__ intrins,
                                    const float* __restrict__ post_rots,
                                    const float* __restrict__ post_trans) {
    __shared__ float sM[48 * 24];
    int t = threadIdx.x;

    if (t < Bn * Nn) {
        int cam = t;
        float M1[9], Ki[9], M2[9];
        inv3(post_rots + cam * 9, M1);
        inv3(intrins + cam * 9, Ki);
        const float* R = rots + cam * 9;
        #pragma unroll
        for (int r = 0; r < 3; r++)
            #pragma unroll
            for (int c = 0; c < 3; c++)
                M2[r * 3 + c] = R[r * 3 + 0] * Ki[0 + c] + R[r * 3 + 1] * Ki[3 + c] + R[r * 3 + 2] * Ki[6 + c];
        const float* pt = post_trans + cam * 3;
        float t1[3];
        #pragma unroll
        for (int r = 0; r < 3; r++)
            t1[r] = M1[r * 3 + 0] * pt[0] + M1[r * 3 + 1] * pt[1] + M1[r * 3 + 2] * pt[2];

        float* o = sM + cam * 24;
        #pragma unroll
        for (int k = 0; k < 9; k++) o[k] = M1[k];
        #pragma unroll
        for (int k = 0; k < 3; k++) o[9 + k] = t1[k];
        #pragma unroll
        for (int k = 0; k < 9; k++) o[12 + k] = M2[k];
        const float* tr = trans + cam * 3;
        #pragma unroll
        for (int k = 0; k < 3; k++) o[21 + k] = tr[k];
    }
    __syncthreads();

    int p = blockIdx.x * blockDim.x + t;   // NPRIME divisible by 256

    int b  = p / PTS_PER_B;
    int r  = p - b * PTS_PER_B;
    int n  = r / PTS_PER_N;
    int r2 = r - n * PTS_PER_N;
    int d  = r2 / PTS_PER_D;
    int r3 = r2 - d * PTS_PER_D;
    int h  = r3 / FWn;
    int w  = r3 - h * FWn;

    const float* M = sM + (b * Nn + n) * 24;

    float fx = (float)w * (351.0f / 21.0f);
    float fy = (float)h * (127.0f / 7.0f);
    float fd = 4.0f + (float)d;

    // pt = inv(post_rots) @ (f - post_trans)  ==  M1 @ f - t1
    float px = M[0] * fx + M[1] * fy + M[2] * fd - M[9];
    float py = M[3] * fx + M[4] * fy + M[5] * fd - M[10];
    float pz = M[6] * fx + M[7] * fy + M[8] * fd - M[11];

    // unproject + rotate to ego frame
    float x2 = px * pz;
    float y2 = py * pz;
    float z2 = pz;
    float gxw = M[12] * x2 + M[13] * y2 + M[14] * z2 + M[21];
    float gyw = M[15] * x2 + M[16] * y2 + M[17] * z2 + M[22];
    float gzw = M[18] * x2 + M[19] * y2 + M[20] * z2 + M[23];

    // voxelize (truncate toward zero matches astype(int32))
    int gx = (int)((gxw + 50.0f) / 0.5f);
    int gy = (int)((gyw + 50.0f) / 0.5f);
    int gz = (int)((gzw + 10.0f) / 20.0f);

    bool kept = (gx >= 0) && (gx < NX0) && (gy >= 0) && (gy < NX1) && (gz == 0);

    int vox = 0;
    if (kept) {
        vox = b * VOX_PER_B + gx * NX1 + gy;
        g_touched[vox >> 6] = 1;           // flag before atomics (program order)
    }

    unsigned km = __ballot_sync(0xffffffffu, kept);
    int lane = t & 31;
    int half = lane >> 4;                  // 0: first kept point, 1: second
    int q    = lane & 15;                  // channel-quad

    while (km) {
        int l0 = __ffs(km) - 1; km &= km - 1;
        int l1 = -1;
        if (km) { l1 = __ffs(km) - 1; km &= km - 1; }
        int sl  = (l1 >= 0) ? l1 : l0;     // valid lane for shfl
        int pp0 = __shfl_sync(0xffffffffu, p, l0);
        int vv0 = __shfl_sync(0xffffffffu, vox, l0);
        int pp1 = __shfl_sync(0xffffffffu, p, sl);
        int vv1 = __shfl_sync(0xffffffffu, vox, sl);
        int pp  = half ? pp1 : pp0;
        int vv  = half ? vv1 : vv0;
        if (half == 0 || l1 >= 0) {
            float4 v = __ldcs(&feats[(size_t)pp * 16 + q]);
            atomicAdd(reinterpret_cast<float4*>(g_scratch) + (size_t)vv * 16 + q, v);
        }
    }
}

// ---------------------------------------------------------------------------
// K2: finalize. Untouched -> zeros to out; touched -> transpose scratch tile.
__global__ void finalize_kernel(float* __restrict__ out) {
    __shared__ float tile[64][65];
    int blk  = blockIdx.x;                 // NTILES
    int b    = blk / TILES_PER_B;
    int tIdx = blk - b * TILES_PER_B;
    int pos0 = tIdx * 64;
    int t    = threadIdx.x;                // 256

    float* dst = out + (size_t)b * Cn * VOX_PER_B + pos0;

    if (g_touched[blk] == 0) {
        float4 z = make_float4(0.f, 0.f, 0.f, 0.f);
        #pragma unroll
        for (int k = 0; k < 4; k++) {
            int i = t + 256 * k;           // 0..1023 float4 slots
            int c = i >> 4;
            int p = (i & 15) * 4;
            __stcs(reinterpret_cast<float4*>(dst + (size_t)c * VOX_PER_B + p), z);
        }
        return;
    }

    const float4* src4 = reinterpret_cast<const float4*>(g_scratch) + (size_t)blk * 1024;
    #pragma unroll
    for (int k = 0; k < 4; k++) {
        int i = t + 256 * k;
        float4 v = __ldcs(&src4[i]);       // single-use: evict-first
        int pos = i >> 4;
        int c4  = (i & 15) * 4;
        tile[pos][c4 + 0] = v.x;
        tile[pos][c4 + 1] = v.y;
        tile[pos][c4 + 2] = v.z;
        tile[pos][c4 + 3] = v.w;
    }
    __syncthreads();

    #pragma unroll
    for (int k = 0; k < 4; k++) {
        int i = t + 256 * k;
        int c = i >> 4;
        int p = (i & 15) * 4;
        float4 v = make_float4(tile[p + 0][c], tile[p + 1][c],
                               tile[p + 2][c], tile[p + 3][c]);
        __stcs(reinterpret_cast<float4*>(dst + (size_t)c * VOX_PER_B + p), v);
    }
}

// ---------------------------------------------------------------------------
extern "C" void kernel_launch(void* const* d_in, const int* in_sizes, int n_in,
                              void* d_out, int out_size) {
    const float* x_feats    = (const float*)d_in[0];
    const float* rots       = (const float*)d_in[1];
    const float* trans      = (const float*)d_in[2];
    const float* intrins    = (const float*)d_in[3];
    const float* post_rots  = (const float*)d_in[4];
    const float* post_trans = (const float*)d_in[5];
    float* out = (float*)d_out;

    clean_kernel<<<NTILES / 4, 256>>>();
    geom_scatter_kernel<<<NPRIME / 256, 256>>>(
        reinterpret_cast<const float4*>(x_feats),
        rots, trans, intrins, post_rots, post_trans);
    finalize_kernel<<<NTILES, 256>>>(out);
}